// round 1
// baseline (speedup 1.0000x reference)
#include <cuda_runtime.h>

// ---------------------------------------------------------------------------
// SSTGFAttention: window attention (ws = 1 x 64 x 2) + LePE depthwise conv
// + output projection.  B=2, D=8, H=64, W=64, C=96, heads=4, head_dim=24.
// ---------------------------------------------------------------------------

namespace {
constexpr int B_ = 2, D_ = 8, H_ = 64, W_ = 64, C_ = 96;
constexpr int NH_ = 4, HD_ = 24, NTOK_ = 128;
constexpr int NWIN_ = B_ * D_ * (W_ / 2);       // 512
constexpr int RS_ = 100;                         // padded smem row stride (floats)
constexpr int TENSZ_ = B_ * D_ * H_ * W_ * C_;   // 6,291,456
constexpr float SCALE_ = 0.10206207261596577f;   // (384/4)^-0.5 = 1/sqrt(96)
}

// scratch for LePE result (allowed: __device__ global array)
__device__ float g_lepe[TENSZ_];

// ---------------------------------------------------------------------------
// Kernel 1: depthwise 3x3x3 conv over v -> g_lepe  (zero padding)
// one thread = one token x 4 channels (float4)
// ---------------------------------------------------------------------------
__global__ void lepe_kernel(const float* __restrict__ v,
                            const float* __restrict__ cw,
                            const float* __restrict__ cb) {
    __shared__ float sw[C_ * 27];
    __shared__ float sb[C_];
    for (int i = threadIdx.x; i < C_ * 27; i += blockDim.x) sw[i] = cw[i];
    if (threadIdx.x < C_) sb[threadIdx.x] = cb[threadIdx.x];
    __syncthreads();

    int g = blockIdx.x * blockDim.x + threadIdx.x;   // (token, cgroup)
    int cg  = g % (C_ / 4);
    int tok = g / (C_ / 4);
    int w  = tok % W_;
    int h  = (tok / W_) % H_;
    int d  = (tok / (W_ * H_)) % D_;
    int bb = tok / (W_ * H_ * D_);
    int c0 = cg * 4;

    float a0 = sb[c0], a1 = sb[c0 + 1], a2 = sb[c0 + 2], a3 = sb[c0 + 3];

    #pragma unroll
    for (int kd = 0; kd < 3; kd++) {
        int dz = d + kd - 1;
        if (dz < 0 || dz >= D_) continue;
        #pragma unroll
        for (int kh = 0; kh < 3; kh++) {
            int hz = h + kh - 1;
            if (hz < 0 || hz >= H_) continue;
            #pragma unroll
            for (int kw = 0; kw < 3; kw++) {
                int wz = w + kw - 1;
                if (wz < 0 || wz >= W_) continue;
                int off = (((bb * D_ + dz) * H_ + hz) * W_ + wz) * C_ + c0;
                float4 vv = *(const float4*)(v + off);
                int tap = kd * 9 + kh * 3 + kw;
                a0 += vv.x * sw[(c0    ) * 27 + tap];
                a1 += vv.y * sw[(c0 + 1) * 27 + tap];
                a2 += vv.z * sw[(c0 + 2) * 27 + tap];
                a3 += vv.w * sw[(c0 + 3) * 27 + tap];
            }
        }
    }
    *(float4*)(g_lepe + tok * C_ + c0) = make_float4(a0, a1, a2, a3);
}

// ---------------------------------------------------------------------------
// Kernel 2: per-window attention + lepe add + projection (fused).
// One CTA per window, 256 threads.
// smem: sK[128][100] | sV[128][100] | sO[128][100]  (153.6 KB dynamic)
// After attention, transposed proj weights overlay the dead sK region.
// ---------------------------------------------------------------------------
__global__ void __launch_bounds__(256, 1)
attn_kernel(const float* __restrict__ qkv,
            const float* __restrict__ pw,
            const float* __restrict__ pb,
            float* __restrict__ out) {
    extern __shared__ float smem[];
    float* sK = smem;
    float* sV = smem + NTOK_ * RS_;
    float* sO = smem + 2 * NTOK_ * RS_;

    const int wid = blockIdx.x;
    const int wb  = wid & 31;          // w-block (W/2 = 32)
    const int d   = (wid >> 5) & 7;
    const int bb  = wid >> 8;
    const int t   = threadIdx.x;

    const float* qg = qkv;
    const float* kg = qkv + TENSZ_;
    const float* vg = qkv + 2 * TENSZ_;
    const int wbase = (((bb * D_ + d) * H_) * W_ + wb * 2) * C_;

    // ---- cooperative load of K, V window tiles (float4) ----
    for (int i = t; i < NTOK_ * 24; i += 256) {
        int n = i / 24;
        int j = (i % 24) * 4;
        int h = n >> 1, wi2 = n & 1;
        int go = wbase + (h * W_ + wi2) * C_ + j;
        float4 k4 = *(const float4*)(kg + go);
        float4 v4 = *(const float4*)(vg + go);
        *(float4*)(sK + n * RS_ + j) = k4;
        *(float4*)(sV + n * RS_ + j) = v4;
    }
    __syncthreads();

    // ---- attention: each thread owns row i for 2 heads ----
    const int row  = t & 127;
    const int hsel = t >> 7;           // 0 or 1 -> heads {hsel*2, hsel*2+1}
    const int myh  = row >> 1, mywi = row & 1;
    const int rowoff = wbase + (myh * W_ + mywi) * C_;

    #pragma unroll 1
    for (int p = 0; p < 2; p++) {
        const int head = hsel * 2 + p;
        const int hc = head * HD_;

        float q[HD_];
        #pragma unroll
        for (int j = 0; j < HD_; j += 4) {
            float4 q4 = *(const float4*)(qg + rowoff + hc + j);
            q[j]     = q4.x * SCALE_;
            q[j + 1] = q4.y * SCALE_;
            q[j + 2] = q4.z * SCALE_;
            q[j + 3] = q4.w * SCALE_;
        }

        float m = -1e30f, l = 0.f;
        float acc[HD_];
        #pragma unroll
        for (int j = 0; j < HD_; j++) acc[j] = 0.f;

        #pragma unroll 1
        for (int j0 = 0; j0 < NTOK_; j0 += 8) {
            float s[8];
            #pragma unroll
            for (int jj = 0; jj < 8; jj++) {
                const float* kr = sK + (j0 + jj) * RS_ + hc;
                float t0 = 0.f, t1 = 0.f, t2 = 0.f, t3 = 0.f;
                #pragma unroll
                for (int hd = 0; hd < HD_; hd += 4) {
                    float4 k4 = *(const float4*)(kr + hd);
                    t0 += q[hd]     * k4.x;
                    t1 += q[hd + 1] * k4.y;
                    t2 += q[hd + 2] * k4.z;
                    t3 += q[hd + 3] * k4.w;
                }
                s[jj] = (t0 + t1) + (t2 + t3);
            }
            float cm = m;
            #pragma unroll
            for (int jj = 0; jj < 8; jj++) cm = fmaxf(cm, s[jj]);
            float sc = __expf(m - cm);
            l *= sc;
            #pragma unroll
            for (int j = 0; j < HD_; j++) acc[j] *= sc;
            #pragma unroll
            for (int jj = 0; jj < 8; jj++) {
                float pv = __expf(s[jj] - cm);
                l += pv;
                const float* vr = sV + (j0 + jj) * RS_ + hc;
                #pragma unroll
                for (int hd = 0; hd < HD_; hd += 4) {
                    float4 v4 = *(const float4*)(vr + hd);
                    acc[hd]     += pv * v4.x;
                    acc[hd + 1] += pv * v4.y;
                    acc[hd + 2] += pv * v4.z;
                    acc[hd + 3] += pv * v4.w;
                }
            }
            m = cm;
        }

        float inv = 1.f / l;
        float* orow = sO + row * RS_ + hc;
        const float* lrow = g_lepe + rowoff + hc;
        #pragma unroll
        for (int hd = 0; hd < HD_; hd += 4) {
            float4 le = *(const float4*)(lrow + hd);
            float4 o4 = make_float4(acc[hd] * inv + le.x,
                                    acc[hd + 1] * inv + le.y,
                                    acc[hd + 2] * inv + le.z,
                                    acc[hd + 3] * inv + le.w);
            *(float4*)(orow + hd) = o4;
        }
    }
    __syncthreads();

    // ---- overlay transposed proj weights into the dead sK region ----
    float* sWt = sK;   // sWt[ci*96 + co] = pw[co*96 + ci]
    for (int i = t; i < C_ * C_; i += 256) {
        int co = i / C_, ci = i % C_;
        sWt[ci * C_ + co] = pw[i];
    }
    __syncthreads();

    // ---- projection: thread = 4 tokens x 12 out-channels ----
    const int tg  = t >> 3;     // 0..31 (token group of 4)
    const int cgp = t & 7;      // 0..7
    const int co0 = cgp * 12;

    float bj[12];
    #pragma unroll
    for (int j = 0; j < 12; j++) bj[j] = pb[co0 + j];

    float y[4][12];
    #pragma unroll
    for (int k = 0; k < 4; k++)
        #pragma unroll
        for (int j = 0; j < 12; j++) y[k][j] = bj[j];

    #pragma unroll 1
    for (int ci = 0; ci < C_; ci++) {
        float a0 = sO[(tg * 4 + 0) * RS_ + ci];
        float a1 = sO[(tg * 4 + 1) * RS_ + ci];
        float a2 = sO[(tg * 4 + 2) * RS_ + ci];
        float a3 = sO[(tg * 4 + 3) * RS_ + ci];
        float4 w0 = *(const float4*)(sWt + ci * C_ + co0);
        float4 w1 = *(const float4*)(sWt + ci * C_ + co0 + 4);
        float4 w2 = *(const float4*)(sWt + ci * C_ + co0 + 8);
        float wv[12] = {w0.x, w0.y, w0.z, w0.w,
                        w1.x, w1.y, w1.z, w1.w,
                        w2.x, w2.y, w2.z, w2.w};
        #pragma unroll
        for (int j = 0; j < 12; j++) {
            y[0][j] += a0 * wv[j];
            y[1][j] += a1 * wv[j];
            y[2][j] += a2 * wv[j];
            y[3][j] += a3 * wv[j];
        }
    }

    #pragma unroll
    for (int k = 0; k < 4; k++) {
        int n = tg * 4 + k;
        int h = n >> 1, wi2 = n & 1;
        int go = wbase + (h * W_ + wi2) * C_ + co0;
        *(float4*)(out + go)     = make_float4(y[k][0], y[k][1], y[k][2],  y[k][3]);
        *(float4*)(out + go + 4) = make_float4(y[k][4], y[k][5], y[k][6],  y[k][7]);
        *(float4*)(out + go + 8) = make_float4(y[k][8], y[k][9], y[k][10], y[k][11]);
    }
}

// ---------------------------------------------------------------------------
extern "C" void kernel_launch(void* const* d_in, const int* in_sizes, int n_in,
                              void* d_out, int out_size) {
    const float* qkv = (const float*)d_in[0];
    const float* cw  = (const float*)d_in[1];
    const float* cb  = (const float*)d_in[2];
    const float* pw  = (const float*)d_in[3];
    const float* pb  = (const float*)d_in[4];
    float* out = (float*)d_out;

    const float* v = qkv + 2 * TENSZ_;

    // LePE depthwise conv -> scratch
    int total = (TENSZ_ / C_) * (C_ / 4);        // 65536 * 24
    lepe_kernel<<<total / 256, 256>>>(v, cw, cb);

    // fused attention + projection
    const int smem_bytes = 3 * NTOK_ * RS_ * (int)sizeof(float);  // 153600
    cudaFuncSetAttribute(attn_kernel,
                         cudaFuncAttributeMaxDynamicSharedMemorySize, smem_bytes);
    attn_kernel<<<NWIN_, 256, smem_bytes>>>(qkv, pw, pb, out);
}

// round 3
// speedup vs baseline: 1.4318x; 1.4318x over previous
#include <cuda_runtime.h>

// ---------------------------------------------------------------------------
// SSTGFAttention: window attention (ws = 1 x 64 x 2) + LePE depthwise conv
// + output projection.  B=2, D=8, H=64, W=64, C=96, heads=4, head_dim=24.
// R3 = R2 design (f32x2 packed math, 96KB smem -> 2 CTAs/SM, 4-token lepe),
// re-benched after infra failure; minor scheduling micro-fixes.
// ---------------------------------------------------------------------------

typedef unsigned long long u64;

__device__ __forceinline__ u64 ffma2(u64 a, u64 b, u64 c) {
    u64 d; asm("fma.rn.f32x2 %0,%1,%2,%3;" : "=l"(d) : "l"(a), "l"(b), "l"(c)); return d;
}
__device__ __forceinline__ u64 fmul2(u64 a, u64 b) {
    u64 d; asm("mul.rn.f32x2 %0,%1,%2;" : "=l"(d) : "l"(a), "l"(b)); return d;
}
__device__ __forceinline__ u64 fadd2(u64 a, u64 b) {
    u64 d; asm("add.rn.f32x2 %0,%1,%2;" : "=l"(d) : "l"(a), "l"(b)); return d;
}
__device__ __forceinline__ u64 fpack(float lo, float hi) {
    u64 r; asm("mov.b64 %0,{%1,%2};" : "=l"(r) : "f"(lo), "f"(hi)); return r;
}
__device__ __forceinline__ float2 funpack(u64 v) {
    float2 f; asm("mov.b64 {%0,%1},%2;" : "=f"(f.x), "=f"(f.y) : "l"(v)); return f;
}

namespace {
constexpr int B_ = 2, D_ = 8, H_ = 64, W_ = 64, C_ = 96;
constexpr int HD_ = 24, NTOK_ = 128;
constexpr int NWIN_ = B_ * D_ * (W_ / 2);        // 512
constexpr int TENSZ_ = B_ * D_ * H_ * W_ * C_;   // 6,291,456
constexpr float SCALE_ = 0.10206207261596577f;   // 1/sqrt(96)
// smem float offsets (attn kernel): total 24576 floats = 96 KB
constexpr int OFF_V_  = 12288;    // sV after sK [4][128][24]
constexpr int OFF_W_  = 0;        // sWt overlay, stride 100  (96*100 = 9600)
constexpr int WSTR_   = 100;
constexpr int OFF_O_  = 9600;     // sO overlay, stride 98   (128*98 = 12544)
constexpr int OSTR_   = 98;
}

__device__ float g_lepe[TENSZ_];

// ---------------------------------------------------------------------------
// Kernel 1: depthwise 3x3x3 conv of v -> g_lepe.
// Thread = 4 consecutive w-tokens x 4 channels; packed f32x2 accumulation.
// ---------------------------------------------------------------------------
__global__ void __launch_bounds__(256) lepe_kernel(const float* __restrict__ v,
                                                   const float* __restrict__ cw,
                                                   const float* __restrict__ cb) {
    __shared__ u64 spw[27 * 48];     // [tap][channel-pair] packed weights
    __shared__ float sb[C_];
    for (int i = threadIdx.x; i < 27 * 48; i += 256) {
        int tap = i / 48, p = i % 48;
        spw[i] = fpack(cw[(2 * p) * 27 + tap], cw[(2 * p + 1) * 27 + tap]);
    }
    if (threadIdx.x < C_) sb[threadIdx.x] = cb[threadIdx.x];
    __syncthreads();

    int g = blockIdx.x * 256 + threadIdx.x;     // (token-quad, cgroup)
    int cg = g % 24;
    int tq = g / 24;
    int wq = tq & 15;
    int h  = (tq >> 4) & 63;
    int d  = (tq >> 10) & 7;
    int bb = tq >> 13;
    int w0 = wq * 4, c0 = cg * 4, p0 = c0 >> 1;

    u64 acc[4][2];
    {
        u64 b0 = fpack(sb[c0], sb[c0 + 1]);
        u64 b1 = fpack(sb[c0 + 2], sb[c0 + 3]);
        #pragma unroll
        for (int t = 0; t < 4; t++) { acc[t][0] = b0; acc[t][1] = b1; }
    }

    #pragma unroll
    for (int kd = 0; kd < 3; kd++) {
        int dz = d + kd - 1;
        if (dz < 0 || dz >= D_) continue;
        #pragma unroll
        for (int kh = 0; kh < 3; kh++) {
            int hz = h + kh - 1;
            if (hz < 0 || hz >= H_) continue;
            const float* base = v + (((bb * D_ + dz) * H_ + hz) * (size_t)W_) * C_ + c0;
            u64 vv[6][2];
            #pragma unroll
            for (int j = 0; j < 6; j++) {
                int wz = w0 - 1 + j;
                if (wz >= 0 && wz < W_) {
                    ulonglong2 t2 = *(const ulonglong2*)(base + wz * C_);
                    vv[j][0] = t2.x; vv[j][1] = t2.y;
                } else {
                    vv[j][0] = 0ULL; vv[j][1] = 0ULL;
                }
            }
            int tapb = kd * 9 + kh * 3;
            #pragma unroll
            for (int kw = 0; kw < 3; kw++) {
                u64 wA = spw[(tapb + kw) * 48 + p0];
                u64 wB = spw[(tapb + kw) * 48 + p0 + 1];
                #pragma unroll
                for (int t = 0; t < 4; t++) {
                    acc[t][0] = ffma2(vv[t + kw][0], wA, acc[t][0]);
                    acc[t][1] = ffma2(vv[t + kw][1], wB, acc[t][1]);
                }
            }
        }
    }

    int tokbase = ((bb * D_ + d) * H_ + h) * W_ + w0;
    #pragma unroll
    for (int t = 0; t < 4; t++) {
        ulonglong2 o; o.x = acc[t][0]; o.y = acc[t][1];
        *(ulonglong2*)(g_lepe + (size_t)(tokbase + t) * C_ + c0) = o;
    }
}

// ---------------------------------------------------------------------------
// Kernel 2: per-window attention + lepe + projection (fused).
// One CTA per window, 256 threads, 96 KB dynamic smem -> 2 CTAs/SM.
// smem phase 1: sK[4][128][24] | sV[4][128][24]
// smem phase 2: sWt[96][100]   | sO[128][98]   (overlaid after sync)
// ---------------------------------------------------------------------------
__global__ void __launch_bounds__(256, 2)
attn_kernel(const float* __restrict__ qkv,
            const float* __restrict__ pw,
            const float* __restrict__ pb,
            float* __restrict__ out) {
    extern __shared__ float smem[];
    float* sK = smem;
    float* sV = smem + OFF_V_;

    const int wid = blockIdx.x;
    const int wb  = wid & 31;
    const int d   = (wid >> 5) & 7;
    const int bb  = wid >> 8;
    const int t   = threadIdx.x;

    const float* qg = qkv;
    const float* kg = qkv + TENSZ_;
    const float* vg = qkv + 2 * TENSZ_;
    const int wbase = (((bb * D_ + d) * H_) * W_ + wb * 2) * C_;

    // ---- cooperative load K, V -> head-major [head][tok][24] ----
    for (int i = t; i < NTOK_ * 24; i += 256) {
        int tok = i / 24;
        int fg  = i % 24;                 // float4 group within token
        int head = fg / 6;
        int sub  = (fg % 6) * 4;
        int h2 = tok >> 1, wi2 = tok & 1;
        int go = wbase + (h2 * W_ + wi2) * C_ + fg * 4;
        float4 k4 = *(const float4*)(kg + go);
        float4 v4 = *(const float4*)(vg + go);
        int dst = head * (NTOK_ * HD_) + tok * HD_ + sub;
        *(float4*)(sK + dst) = k4;
        *(float4*)(sV + dst) = v4;
    }
    __syncthreads();

    const int row  = t & 127;
    const int hsel = t >> 7;
    const int myh  = row >> 1, mywi = row & 1;
    const int rowoff = wbase + (myh * W_ + mywi) * C_;

    float outv[2][HD_];

    #pragma unroll 1
    for (int p = 0; p < 2; p++) {
        const int head = hsel * 2 + p;
        const int kb = head * (NTOK_ * HD_);

        // q, pre-scaled, packed
        u64 qp[12];
        const float* qptr = qg + rowoff + head * HD_;
        #pragma unroll
        for (int j = 0; j < 6; j++) {
            float4 q4 = *(const float4*)(qptr + j * 4);
            qp[2 * j]     = fpack(q4.x * SCALE_, q4.y * SCALE_);
            qp[2 * j + 1] = fpack(q4.z * SCALE_, q4.w * SCALE_);
        }

        float m = -1e30f, l = 0.f;
        u64 acc[12];
        #pragma unroll
        for (int j = 0; j < 12; j++) acc[j] = 0ULL;

        #pragma unroll 1
        for (int j0 = 0; j0 < NTOK_; j0 += 8) {
            float s[8];
            #pragma unroll
            for (int jj = 0; jj < 8; jj++) {
                const ulonglong2* kr = (const ulonglong2*)(sK + kb + (j0 + jj) * HD_);
                ulonglong2 k0 = kr[0], k1 = kr[1], k2 = kr[2];
                ulonglong2 k3 = kr[3], k4 = kr[4], k5 = kr[5];
                u64 d0 = fmul2(qp[0], k0.x);
                u64 d1 = fmul2(qp[1], k0.y);
                u64 d2 = fmul2(qp[2], k1.x);
                u64 d3 = fmul2(qp[3], k1.y);
                d0 = ffma2(qp[4],  k2.x, d0);
                d1 = ffma2(qp[5],  k2.y, d1);
                d2 = ffma2(qp[6],  k3.x, d2);
                d3 = ffma2(qp[7],  k3.y, d3);
                d0 = ffma2(qp[8],  k4.x, d0);
                d1 = ffma2(qp[9],  k4.y, d1);
                d2 = ffma2(qp[10], k5.x, d2);
                d3 = ffma2(qp[11], k5.y, d3);
                d0 = fadd2(d0, d1);
                d2 = fadd2(d2, d3);
                d0 = fadd2(d0, d2);
                float2 f = funpack(d0);
                s[jj] = f.x + f.y;
            }
            float cm = m;
            #pragma unroll
            for (int jj = 0; jj < 8; jj++) cm = fmaxf(cm, s[jj]);
            float sc = __expf(m - cm);
            l *= sc;
            u64 scp = fpack(sc, sc);
            #pragma unroll
            for (int j = 0; j < 12; j++) acc[j] = fmul2(acc[j], scp);
            #pragma unroll
            for (int jj = 0; jj < 8; jj++) {
                float pv = __expf(s[jj] - cm);
                l += pv;
                u64 pvp = fpack(pv, pv);
                const ulonglong2* vr = (const ulonglong2*)(sV + kb + (j0 + jj) * HD_);
                ulonglong2 v0 = vr[0], v1 = vr[1], v2 = vr[2];
                ulonglong2 v3 = vr[3], v4 = vr[4], v5 = vr[5];
                acc[0]  = ffma2(pvp, v0.x, acc[0]);
                acc[6]  = ffma2(pvp, v3.x, acc[6]);
                acc[1]  = ffma2(pvp, v0.y, acc[1]);
                acc[7]  = ffma2(pvp, v3.y, acc[7]);
                acc[2]  = ffma2(pvp, v1.x, acc[2]);
                acc[8]  = ffma2(pvp, v4.x, acc[8]);
                acc[3]  = ffma2(pvp, v1.y, acc[3]);
                acc[9]  = ffma2(pvp, v4.y, acc[9]);
                acc[4]  = ffma2(pvp, v2.x, acc[4]);
                acc[10] = ffma2(pvp, v5.x, acc[10]);
                acc[5]  = ffma2(pvp, v2.y, acc[5]);
                acc[11] = ffma2(pvp, v5.y, acc[11]);
            }
            m = cm;
        }

        float inv = 1.f / l;
        const float* lrow = g_lepe + rowoff + head * HD_;
        #pragma unroll
        for (int j = 0; j < 12; j++) {
            float2 a  = funpack(acc[j]);
            float2 le = *(const float2*)(lrow + 2 * j);
            outv[p][2 * j]     = a.x * inv + le.x;
            outv[p][2 * j + 1] = a.y * inv + le.y;
        }
    }
    __syncthreads();   // K, V dead from here

    // ---- overlay: write O tiles, load transposed proj weights ----
    float* sWt = smem + OFF_W_;           // [ci][100], col co
    float* sO  = smem + OFF_O_;           // [tok][98]
    #pragma unroll
    for (int p = 0; p < 2; p++) {
        float* orow = sO + row * OSTR_ + (hsel * 2 + p) * HD_;
        #pragma unroll
        for (int j = 0; j < 12; j++)
            *(float2*)(orow + 2 * j) = make_float2(outv[p][2 * j], outv[p][2 * j + 1]);
    }
    for (int i = t; i < C_ * C_; i += 256) {
        int co = i / C_, ci = i % C_;     // coalesced LDG, transposed STS
        sWt[ci * WSTR_ + co] = pw[i];
    }
    __syncthreads();

    // ---- projection: thread = 4 tokens x 12 out-channels, packed ----
    const int tg  = t >> 3;
    const int cgp = t & 7;
    const int co0 = cgp * 12;

    u64 y[4][6];
    #pragma unroll
    for (int j = 0; j < 6; j++) {
        u64 bj = fpack(pb[co0 + 2 * j], pb[co0 + 2 * j + 1]);
        y[0][j] = bj; y[1][j] = bj; y[2][j] = bj; y[3][j] = bj;
    }

    #pragma unroll 4
    for (int ci = 0; ci < C_; ci++) {
        const ulonglong2* wr = (const ulonglong2*)(sWt + ci * WSTR_ + co0);
        ulonglong2 w0 = wr[0], w1 = wr[1], w2 = wr[2];
        #pragma unroll
        for (int k = 0; k < 4; k++) {
            float a = sO[(tg * 4 + k) * OSTR_ + ci];
            u64 ap = fpack(a, a);
            y[k][0] = ffma2(ap, w0.x, y[k][0]);
            y[k][1] = ffma2(ap, w0.y, y[k][1]);
            y[k][2] = ffma2(ap, w1.x, y[k][2]);
            y[k][3] = ffma2(ap, w1.y, y[k][3]);
            y[k][4] = ffma2(ap, w2.x, y[k][4]);
            y[k][5] = ffma2(ap, w2.y, y[k][5]);
        }
    }

    #pragma unroll
    for (int k = 0; k < 4; k++) {
        int n = tg * 4 + k;
        int h2 = n >> 1, wi2 = n & 1;
        int go = wbase + (h2 * W_ + wi2) * C_ + co0;
        float2 f0 = funpack(y[k][0]), f1 = funpack(y[k][1]);
        float2 f2 = funpack(y[k][2]), f3 = funpack(y[k][3]);
        float2 f4 = funpack(y[k][4]), f5 = funpack(y[k][5]);
        *(float4*)(out + go)     = make_float4(f0.x, f0.y, f1.x, f1.y);
        *(float4*)(out + go + 4) = make_float4(f2.x, f2.y, f3.x, f3.y);
        *(float4*)(out + go + 8) = make_float4(f4.x, f4.y, f5.x, f5.y);
    }
}

// ---------------------------------------------------------------------------
extern "C" void kernel_launch(void* const* d_in, const int* in_sizes, int n_in,
                              void* d_out, int out_size) {
    const float* qkv = (const float*)d_in[0];
    const float* cw  = (const float*)d_in[1];
    const float* cb  = (const float*)d_in[2];
    const float* pw  = (const float*)d_in[3];
    const float* pb  = (const float*)d_in[4];
    float* out = (float*)d_out;

    const float* v = qkv + 2 * TENSZ_;

    // LePE depthwise conv -> scratch (4 tokens x 4 ch per thread)
    int threads_total = (TENSZ_ / C_ / 4) * 24;   // 393216
    lepe_kernel<<<threads_total / 256, 256>>>(v, cw, cb);

    // fused attention + projection
    const int smem_bytes = 24576 * (int)sizeof(float);   // 98304
    cudaFuncSetAttribute(attn_kernel,
                         cudaFuncAttributeMaxDynamicSharedMemorySize, smem_bytes);
    attn_kernel<<<NWIN_, 256, smem_bytes>>>(qkv, pw, pb, out);
}